// round 5
// baseline (speedup 1.0000x reference)
#include <cuda_runtime.h>
#include <cuda_bf16.h>
#include <cstdint>

#define NU 100000          // users
#define NM 20000           // movies
#define NE 1000000         // edges per direction
#define NLOOP 20000        // self loops (min(NU,NM))
#define ET (NE + NLOOP)
#define HD 64

// ---------------- scratch (static device globals) ---------------------------
__device__ int   g_cntm[NM],   g_cntu[NU];
__device__ int   g_offm[NM+1], g_offu[NU+1];
__device__ int   g_curm[NM],   g_curu[NU];
__device__ int2  g_csrm[ET],   g_csru[ET];    // (src,dst), dst-sorted
__device__ float g_sm[NM],     g_su[NU];      // segment sums of exp
__device__ float g_accm[(size_t)NM * HD];
__device__ float g_accu[(size_t)NU * HD];
__device__ float g_xlu[(size_t)NU * HD];   // user  src-proj (xl of u2m)
__device__ float g_xru[(size_t)NU * HD];   // user  dst-proj (xr of m2u)
__device__ float g_xlm[(size_t)NM * HD];   // movie src-proj (xl of m2u)
__device__ float g_xrm[(size_t)NM * HD];   // movie dst-proj (xr of u2m)
__device__ float g_xu[(size_t)NU * HD];    // layer-0 user output
__device__ float g_xm[(size_t)NM * HD];    // layer-0 movie output

// ---------------- CSR build --------------------------------------------------
__global__ void zero_k(int* __restrict__ p, int n)
{
    int i = blockIdx.x * blockDim.x + threadIdx.x;
    if (i < n) p[i] = 0;
}

__global__ void hist_k(const int* __restrict__ edst, int* __restrict__ cnt)
{
    int e = blockIdx.x * blockDim.x + threadIdx.x;
    if (e >= ET) return;
    int d = (e < NE) ? edst[e] : e - NE;
    atomicAdd(&cnt[d], 1);
}

__global__ void scan_k(const int* __restrict__ cnt, int* __restrict__ off,
                       int* __restrict__ cur, int n)
{
    __shared__ int part[1024];
    int t = threadIdx.x;
    int chunk = (n + 1023) >> 10;
    int b = t * chunk;
    int e = min(b + chunk, n);
    int s = 0;
    for (int i = b; i < e; i++) s += cnt[i];
    part[t] = s;
    __syncthreads();
    for (int o = 1; o < 1024; o <<= 1) {
        int v = (t >= o) ? part[t - o] : 0;
        __syncthreads();
        part[t] += v;
        __syncthreads();
    }
    int run = (t == 0) ? 0 : part[t - 1];
    for (int i = b; i < e; i++) {
        off[i] = run; cur[i] = run;
        run += cnt[i];
    }
    if (t == 1023) off[n] = part[1023];
}

__global__ void reorder_k(const int* __restrict__ esrc, const int* __restrict__ edst,
                          int* __restrict__ cur, int2* __restrict__ csr)
{
    int e = blockIdx.x * blockDim.x + threadIdx.x;
    if (e >= ET) return;
    int s, d;
    if (e < NE) { s = esrc[e]; d = edst[e]; } else { s = e - NE; d = s; }
    int pos = atomicAdd(&cur[d], 1);
    csr[pos] = make_int2(s, d);
}

// ---------------- dual-output GEMM: Y1 = X@W1+B1, Y2 = X@W2+B2 ---------------
__global__ void gemm2_k(const float* __restrict__ X,
                        const float* __restrict__ W1, const float* __restrict__ B1,
                        const float* __restrict__ W2, const float* __restrict__ B2,
                        float* __restrict__ Y1, float* __restrict__ Y2, int N)
{
    __shared__ float Xs[64][65];
    __shared__ float Ws1[64][64];
    __shared__ float Ws2[64][64];
    int tid  = threadIdx.x;              // 256 threads
    int row0 = blockIdx.x * 64;

#pragma unroll
    for (int i = 0; i < 4; i++) {
        ((float4*)Ws1)[tid + i * 256] = ((const float4*)W1)[tid + i * 256];
        ((float4*)Ws2)[tid + i * 256] = ((const float4*)W2)[tid + i * 256];
    }
#pragma unroll
    for (int i = 0; i < 4; i++) {
        int idx = tid + i * 256;
        int r = idx >> 4, c4 = idx & 15;
        float4 v = make_float4(0.f, 0.f, 0.f, 0.f);
        if (row0 + r < N) v = ((const float4*)X)[(size_t)(row0 + r) * 16 + c4];
        Xs[r][c4 * 4 + 0] = v.x; Xs[r][c4 * 4 + 1] = v.y;
        Xs[r][c4 * 4 + 2] = v.z; Xs[r][c4 * 4 + 3] = v.w;
    }
    __syncthreads();

    int ty = tid >> 4, tx = tid & 15;
    float a1[4][4], a2[4][4];
#pragma unroll
    for (int i = 0; i < 4; i++)
#pragma unroll
        for (int j = 0; j < 4; j++) { a1[i][j] = 0.f; a2[i][j] = 0.f; }

#pragma unroll
    for (int k = 0; k < 64; k++) {
        float4 w1 = ((const float4*)Ws1)[k * 16 + tx];
        float4 w2 = ((const float4*)Ws2)[k * 16 + tx];
        float x0 = Xs[ty * 4 + 0][k];
        float x1 = Xs[ty * 4 + 1][k];
        float x2 = Xs[ty * 4 + 2][k];
        float x3 = Xs[ty * 4 + 3][k];
        a1[0][0] += x0*w1.x; a1[0][1] += x0*w1.y; a1[0][2] += x0*w1.z; a1[0][3] += x0*w1.w;
        a1[1][0] += x1*w1.x; a1[1][1] += x1*w1.y; a1[1][2] += x1*w1.z; a1[1][3] += x1*w1.w;
        a1[2][0] += x2*w1.x; a1[2][1] += x2*w1.y; a1[2][2] += x2*w1.z; a1[2][3] += x2*w1.w;
        a1[3][0] += x3*w1.x; a1[3][1] += x3*w1.y; a1[3][2] += x3*w1.z; a1[3][3] += x3*w1.w;
        a2[0][0] += x0*w2.x; a2[0][1] += x0*w2.y; a2[0][2] += x0*w2.z; a2[0][3] += x0*w2.w;
        a2[1][0] += x1*w2.x; a2[1][1] += x1*w2.y; a2[1][2] += x1*w2.z; a2[1][3] += x1*w2.w;
        a2[2][0] += x2*w2.x; a2[2][1] += x2*w2.y; a2[2][2] += x2*w2.z; a2[2][3] += x2*w2.w;
        a2[3][0] += x3*w2.x; a2[3][1] += x3*w2.y; a2[3][2] += x3*w2.z; a2[3][3] += x3*w2.w;
    }

    float4 b1 = ((const float4*)B1)[tx];
    float4 b2 = ((const float4*)B2)[tx];
#pragma unroll
    for (int i = 0; i < 4; i++) {
        int r = row0 + ty * 4 + i;
        if (r < N) {
            float4 o1, o2;
            o1.x = a1[i][0] + b1.x; o1.y = a1[i][1] + b1.y;
            o1.z = a1[i][2] + b1.z; o1.w = a1[i][3] + b1.w;
            o2.x = a2[i][0] + b2.x; o2.y = a2[i][1] + b2.y;
            o2.z = a2[i][2] + b2.z; o2.w = a2[i][3] + b2.w;
            ((float4*)Y1)[(size_t)r * 16 + tx] = o1;
            ((float4*)Y2)[(size_t)r * 16 + tx] = o2;
        }
    }
}

// ---------------- per-conv init ---------------------------------------------
__global__ void init_k(float* __restrict__ sbuf, float* __restrict__ acc, int ndst)
{
    int i = blockIdx.x * blockDim.x + threadIdx.x;
    int n4 = ndst * (HD / 4);
    if (i < n4) ((float4*)acc)[i] = make_float4(0.f, 0.f, 0.f, 0.f);
    if (i < ndst) sbuf[i] = 0.f;
}

// ---------------- conv: dst-sorted edges, 2 per warp, pair-merged reds -------
__global__ void conv_pair_k(const int2* __restrict__ csr,
                            const float* __restrict__ xl, const float* __restrict__ xr,
                            const float* __restrict__ att,
                            float* __restrict__ sbuf, float* __restrict__ acc)
{
    int t = blockIdx.x * blockDim.x + threadIdx.x;
    int w = t >> 5;
    int lane = threadIdx.x & 31;
    int half = lane >> 4;
    int l16  = lane & 15;
    long e = (long)w * 2 + half;
    bool v = e < ET;

    int2 ed = v ? csr[e] : make_int2(0, -1);
    int s = ed.x, d = ed.y;

    float4 w4 = ((const float4*)att)[l16];
    float4 a = make_float4(0.f, 0.f, 0.f, 0.f);
    float4 b = make_float4(0.f, 0.f, 0.f, 0.f);
    if (v) {
        a = ((const float4*)xl)[(size_t)s * 16 + l16];
        b = ((const float4*)xr)[(size_t)d * 16 + l16];
    }

    float vx = a.x + b.x; vx = vx > 0.f ? vx : 0.2f * vx;
    float vy = a.y + b.y; vy = vy > 0.f ? vy : 0.2f * vy;
    float vz = a.z + b.z; vz = vz > 0.f ? vz : 0.2f * vz;
    float vw = a.w + b.w; vw = vw > 0.f ? vw : 0.2f * vw;
    float p = vx * w4.x + vy * w4.y + vz * w4.z + vw * w4.w;
#pragma unroll
    for (int o = 8; o > 0; o >>= 1) p += __shfl_xor_sync(0xffffffffu, p, o);
    float ex = v ? __expf(p) : 0.f;

    float4 acc4;
    acc4.x = ex * a.x; acc4.y = ex * a.y; acc4.z = ex * a.z; acc4.w = ex * a.w;

    // exchange with partner half (lane ^ 16): same feature dims, other edge
    int   dpart = __shfl_xor_sync(0xffffffffu, d, 16);
    float ox = __shfl_xor_sync(0xffffffffu, acc4.x, 16);
    float oy = __shfl_xor_sync(0xffffffffu, acc4.y, 16);
    float oz = __shfl_xor_sync(0xffffffffu, acc4.z, 16);
    float ow = __shfl_xor_sync(0xffffffffu, acc4.w, 16);
    float oe = __shfl_xor_sync(0xffffffffu, ex,     16);

    bool merge = (d == dpart) && (d >= 0);   // warp-uniform
    if (merge) {
        if (half == 0) {
            acc4.x += ox; acc4.y += oy; acc4.z += oz; acc4.w += ow;
            float* pp = acc + (size_t)d * HD + l16 * 4;
            asm volatile("red.global.add.v4.f32 [%0], {%1,%2,%3,%4};"
                         :: "l"(pp), "f"(acc4.x), "f"(acc4.y), "f"(acc4.z), "f"(acc4.w) : "memory");
            if (l16 == 0) atomicAdd(&sbuf[d], ex + oe);
        }
    } else if (v) {
        float* pp = acc + (size_t)d * HD + l16 * 4;
        asm volatile("red.global.add.v4.f32 [%0], {%1,%2,%3,%4};"
                     :: "l"(pp), "f"(acc4.x), "f"(acc4.y), "f"(acc4.z), "f"(acc4.w) : "memory");
        if (l16 == 0) atomicAdd(&sbuf[d], ex);
    }
}

// ---------------- finalize: /segsum, + bias, SELU ---------------------------
__global__ void finalize_k(const float* __restrict__ acc, const float* __restrict__ sbuf,
                           const float* __restrict__ bias, float* __restrict__ out, int n)
{
    int i = blockIdx.x * blockDim.x + threadIdx.x;
    if (i >= n) return;
    float inv = 1.f / (sbuf[i >> 6] + 1e-16f);
    float x = acc[i] * inv + bias[i & 63];
    const float SCALE = 1.0507009873554805f;
    const float SA    = 1.7580993408473766f;   // scale * alpha
    out[i] = x > 0.f ? SCALE * x : SA * (__expf(x) - 1.f);
}

// ---------------- host ------------------------------------------------------
extern "C" void kernel_launch(void* const* d_in, const int* in_sizes, int n_in,
                              void* d_out, int out_size)
{
    const float* x_user  = (const float*)d_in[0];
    const float* x_movie = (const float*)d_in[1];
    const int*   e_u2m   = (const int*)d_in[2];
    const int*   e_m2u   = (const int*)d_in[3];
    const float* Wl      = (const float*)d_in[4];
    const float* bl      = (const float*)d_in[5];
    const float* Wr      = (const float*)d_in[6];
    const float* br      = (const float*)d_in[7];
    const float* att     = (const float*)d_in[8];
    const float* bias    = (const float*)d_in[9];
    float* out = (float*)d_out;

    int *cntm, *cntu, *offm, *offu, *curm, *curu;
    int2 *csrm, *csru;
    float *sm, *su, *accm, *accu, *xlu, *xru, *xlm, *xrm, *xu, *xm;
    cudaGetSymbolAddress((void**)&cntm, g_cntm);
    cudaGetSymbolAddress((void**)&cntu, g_cntu);
    cudaGetSymbolAddress((void**)&offm, g_offm);
    cudaGetSymbolAddress((void**)&offu, g_offu);
    cudaGetSymbolAddress((void**)&curm, g_curm);
    cudaGetSymbolAddress((void**)&curu, g_curu);
    cudaGetSymbolAddress((void**)&csrm, g_csrm);
    cudaGetSymbolAddress((void**)&csru, g_csru);
    cudaGetSymbolAddress((void**)&sm,   g_sm);
    cudaGetSymbolAddress((void**)&su,   g_su);
    cudaGetSymbolAddress((void**)&accm, g_accm);
    cudaGetSymbolAddress((void**)&accu, g_accu);
    cudaGetSymbolAddress((void**)&xlu,  g_xlu);
    cudaGetSymbolAddress((void**)&xru,  g_xru);
    cudaGetSymbolAddress((void**)&xlm,  g_xlm);
    cudaGetSymbolAddress((void**)&xrm,  g_xrm);
    cudaGetSymbolAddress((void**)&xu,   g_xu);
    cudaGetSymbolAddress((void**)&xm,   g_xm);

    const int EB = (ET + 255) / 256;

    // ---- build dst-sorted edge lists, reused by both layers ----------------
    zero_k<<<(NM + 255) / 256, 256>>>(cntm, NM);
    zero_k<<<(NU + 255) / 256, 256>>>(cntu, NU);
    hist_k<<<EB, 256>>>(e_u2m + NE, cntm);
    hist_k<<<EB, 256>>>(e_m2u + NE, cntu);
    scan_k<<<1, 1024>>>(cntm, offm, curm, NM);
    scan_k<<<1, 1024>>>(cntu, offu, curu, NU);
    reorder_k<<<EB, 256>>>(e_u2m, e_u2m + NE, curm, csrm);
    reorder_k<<<EB, 256>>>(e_m2u, e_m2u + NE, curu, csru);

    const long NW    = (ET + 1) / 2;                 // 2 edges per warp
    const int  CONVB = (int)((NW * 32 + 255) / 256);

    const float* cu = x_user;
    const float* cm = x_movie;

    for (int l = 0; l < 2; l++) {
        int p0 = l * 2 + 0;   // user -> movie
        int p1 = l * 2 + 1;   // movie -> user

        gemm2_k<<<(NU + 63) / 64, 256>>>(cu,
            Wl + (size_t)p0 * 4096, bl + (size_t)p0 * 64,
            Wr + (size_t)p1 * 4096, br + (size_t)p1 * 64, xlu, xru, NU);
        gemm2_k<<<(NM + 63) / 64, 256>>>(cm,
            Wl + (size_t)p1 * 4096, bl + (size_t)p1 * 64,
            Wr + (size_t)p0 * 4096, br + (size_t)p0 * 64, xlm, xrm, NM);

        init_k<<<(NM * (HD / 4) + 255) / 256, 256>>>(sm, accm, NM);
        init_k<<<(NU * (HD / 4) + 255) / 256, 256>>>(su, accu, NU);

        conv_pair_k<<<CONVB, 256>>>(csrm, xlu, xrm, att + (size_t)p0 * 64, sm, accm);
        conv_pair_k<<<CONVB, 256>>>(csru, xlm, xru, att + (size_t)p1 * 64, su, accu);

        float* om = (l == 1) ? (out + (size_t)NU * HD) : xm;
        float* ou = (l == 1) ? out : xu;
        finalize_k<<<(NM * HD + 255) / 256, 256>>>(accm, sm, bias + (size_t)p0 * 64, om, NM * HD);
        finalize_k<<<(NU * HD + 255) / 256, 256>>>(accu, su, bias + (size_t)p1 * 64, ou, NU * HD);

        cu = xu;
        cm = xm;
    }
}

// round 6
// speedup vs baseline: 1.6254x; 1.6254x over previous
#include <cuda_runtime.h>
#include <cuda_bf16.h>
#include <cstdint>

#define NU 100000          // users
#define NM 20000           // movies
#define NE 1000000         // edges per direction
#define NLOOP 20000        // self loops (min(NU,NM))
#define ET (NE + NLOOP)
#define HD 64

// ---------------- scratch (static device globals) ---------------------------
__device__ float g_sm[NM],   g_su[NU];        // segment sums of exp
__device__ float g_accm[(size_t)NM * HD];
__device__ float g_accu[(size_t)NU * HD];
__device__ float g_xlu[(size_t)NU * HD];   // user  src-proj (xl of u2m)
__device__ float g_xru[(size_t)NU * HD];   // user  dst-proj (xr of m2u)
__device__ float g_xlm[(size_t)NM * HD];   // movie src-proj (xl of m2u)
__device__ float g_xrm[(size_t)NM * HD];   // movie dst-proj (xr of u2m)
__device__ float g_xu[(size_t)NU * HD];    // layer-0 user output
__device__ float g_xm[(size_t)NM * HD];    // layer-0 movie output

// ---------------- dual-side, dual-output GEMM --------------------------------
// blocks [0,GU): user rows,  Y1=Xu@W1u+B1u (xl of u2m), Y2=Xu@W2u+B2u (xr of m2u)
// blocks [GU,..): movie rows, Y1=Xm@W1m+B1m (xl of m2u), Y2=Xm@W2m+B2m (xr of u2m)
__global__ void gemm2_dual_k(const float* __restrict__ Xu, const float* __restrict__ Xm,
                             const float* __restrict__ W1u, const float* __restrict__ B1u,
                             const float* __restrict__ W2u, const float* __restrict__ B2u,
                             const float* __restrict__ W1m, const float* __restrict__ B1m,
                             const float* __restrict__ W2m, const float* __restrict__ B2m,
                             float* __restrict__ Y1u, float* __restrict__ Y2u,
                             float* __restrict__ Y1m, float* __restrict__ Y2m,
                             int GU)
{
    __shared__ float Xs[64][65];
    __shared__ float Ws1[64][64];
    __shared__ float Ws2[64][64];
    int tid = threadIdx.x;               // 256 threads
    int bid = blockIdx.x;

    const float *X, *W1, *B1, *W2, *B2;
    float *Y1, *Y2;
    int N;
    if (bid < GU) {
        X = Xu; W1 = W1u; B1 = B1u; W2 = W2u; B2 = B2u;
        Y1 = Y1u; Y2 = Y2u; N = NU;
    } else {
        bid -= GU;
        X = Xm; W1 = W1m; B1 = B1m; W2 = W2m; B2 = B2m;
        Y1 = Y1m; Y2 = Y2m; N = NM;
    }
    int row0 = bid * 64;

#pragma unroll
    for (int i = 0; i < 4; i++) {
        ((float4*)Ws1)[tid + i * 256] = ((const float4*)W1)[tid + i * 256];
        ((float4*)Ws2)[tid + i * 256] = ((const float4*)W2)[tid + i * 256];
    }
#pragma unroll
    for (int i = 0; i < 4; i++) {
        int idx = tid + i * 256;
        int r = idx >> 4, c4 = idx & 15;
        float4 v = make_float4(0.f, 0.f, 0.f, 0.f);
        if (row0 + r < N) v = ((const float4*)X)[(size_t)(row0 + r) * 16 + c4];
        Xs[r][c4 * 4 + 0] = v.x; Xs[r][c4 * 4 + 1] = v.y;
        Xs[r][c4 * 4 + 2] = v.z; Xs[r][c4 * 4 + 3] = v.w;
    }
    __syncthreads();

    int ty = tid >> 4, tx = tid & 15;
    float a1[4][4], a2[4][4];
#pragma unroll
    for (int i = 0; i < 4; i++)
#pragma unroll
        for (int j = 0; j < 4; j++) { a1[i][j] = 0.f; a2[i][j] = 0.f; }

#pragma unroll
    for (int k = 0; k < 64; k++) {
        float4 w1 = ((const float4*)Ws1)[k * 16 + tx];
        float4 w2 = ((const float4*)Ws2)[k * 16 + tx];
        float x0 = Xs[ty * 4 + 0][k];
        float x1 = Xs[ty * 4 + 1][k];
        float x2 = Xs[ty * 4 + 2][k];
        float x3 = Xs[ty * 4 + 3][k];
        a1[0][0] += x0*w1.x; a1[0][1] += x0*w1.y; a1[0][2] += x0*w1.z; a1[0][3] += x0*w1.w;
        a1[1][0] += x1*w1.x; a1[1][1] += x1*w1.y; a1[1][2] += x1*w1.z; a1[1][3] += x1*w1.w;
        a1[2][0] += x2*w1.x; a1[2][1] += x2*w1.y; a1[2][2] += x2*w1.z; a1[2][3] += x2*w1.w;
        a1[3][0] += x3*w1.x; a1[3][1] += x3*w1.y; a1[3][2] += x3*w1.z; a1[3][3] += x3*w1.w;
        a2[0][0] += x0*w2.x; a2[0][1] += x0*w2.y; a2[0][2] += x0*w2.z; a2[0][3] += x0*w2.w;
        a2[1][0] += x1*w2.x; a2[1][1] += x1*w2.y; a2[1][2] += x1*w2.z; a2[1][3] += x1*w2.w;
        a2[2][0] += x2*w2.x; a2[2][1] += x2*w2.y; a2[2][2] += x2*w2.z; a2[2][3] += x2*w2.w;
        a2[3][0] += x3*w2.x; a2[3][1] += x3*w2.y; a2[3][2] += x3*w2.z; a2[3][3] += x3*w2.w;
    }

    float4 b1 = ((const float4*)B1)[tx];
    float4 b2 = ((const float4*)B2)[tx];
#pragma unroll
    for (int i = 0; i < 4; i++) {
        int r = row0 + ty * 4 + i;
        if (r < N) {
            float4 o1, o2;
            o1.x = a1[i][0] + b1.x; o1.y = a1[i][1] + b1.y;
            o1.z = a1[i][2] + b1.z; o1.w = a1[i][3] + b1.w;
            o2.x = a2[i][0] + b2.x; o2.y = a2[i][1] + b2.y;
            o2.z = a2[i][2] + b2.z; o2.w = a2[i][3] + b2.w;
            ((float4*)Y1)[(size_t)r * 16 + tx] = o1;
            ((float4*)Y2)[(size_t)r * 16 + tx] = o2;
        }
    }
}

// ---------------- init both accumulators + both segment sums -----------------
__global__ void init2_k(float* __restrict__ sm_, float* __restrict__ accm,
                        float* __restrict__ su_, float* __restrict__ accu)
{
    int i = blockIdx.x * blockDim.x + threadIdx.x;
    const int NM4 = NM * (HD / 4);
    const int NT4 = (NM + NU) * (HD / 4);
    float4 z = make_float4(0.f, 0.f, 0.f, 0.f);
    if (i < NM4) ((float4*)accm)[i] = z;
    else if (i < NT4) ((float4*)accu)[i - NM4] = z;
    if (i < NM) sm_[i] = 0.f;
    if (i < NU) su_[i] = 0.f;
}

// ---------------- fused edge pass, both directions in one launch -------------
// blocks [0,CB): u2m (xl=user proj, xr=movie proj, dst=movies)
// blocks [CB,2CB): m2u (xl=movie proj, xr=user proj, dst=users)
__global__ void conv_dual_k(const int* __restrict__ eu, const int* __restrict__ em,
                            const float* __restrict__ xlu, const float* __restrict__ xrm,
                            const float* __restrict__ xlm, const float* __restrict__ xru,
                            const float* __restrict__ att0, const float* __restrict__ att1,
                            float* __restrict__ sm_, float* __restrict__ su_,
                            float* __restrict__ accm, float* __restrict__ accu,
                            int CB)
{
    const int *esrc, *edst;
    const float *xl, *xr, *att;
    float *sbuf, *acc;
    int bid = blockIdx.x;
    if (bid < CB) {
        esrc = eu; edst = eu + NE; xl = xlu; xr = xrm; att = att0;
        sbuf = sm_; acc = accm;
    } else {
        bid -= CB;
        esrc = em; edst = em + NE; xl = xlm; xr = xru; att = att1;
        sbuf = su_; acc = accu;
    }

    int t = bid * blockDim.x + threadIdx.x;
    int g = t >> 4;
    if (g >= ET) return;
    int lane = t & 15;
    int s, d;
    if (g < NE) { s = esrc[g]; d = edst[g]; } else { s = g - NE; d = s; }

    float4 a = ((const float4*)xl)[(size_t)s * 16 + lane];
    float4 b = ((const float4*)xr)[(size_t)d * 16 + lane];
    float4 w = ((const float4*)att)[lane];

    float vx = a.x + b.x; vx = vx > 0.f ? vx : 0.2f * vx;
    float vy = a.y + b.y; vy = vy > 0.f ? vy : 0.2f * vy;
    float vz = a.z + b.z; vz = vz > 0.f ? vz : 0.2f * vz;
    float vw = a.w + b.w; vw = vw > 0.f ? vw : 0.2f * vw;
    float p = vx * w.x + vy * w.y + vz * w.z + vw * w.w;
#pragma unroll
    for (int o = 8; o > 0; o >>= 1) p += __shfl_xor_sync(0xffffffffu, p, o);
    float ex = __expf(p);

    if (lane == 0) atomicAdd(&sbuf[d], ex);

    a.x *= ex; a.y *= ex; a.z *= ex; a.w *= ex;
    float* pp = acc + (size_t)d * HD + lane * 4;
    asm volatile("red.global.add.v4.f32 [%0], {%1,%2,%3,%4};"
                 :: "l"(pp), "f"(a.x), "f"(a.y), "f"(a.z), "f"(a.w) : "memory");
}

// ---------------- finalize both node types: /segsum, +bias, SELU -------------
__global__ void finalize2_k(const float* __restrict__ accm, const float* __restrict__ sm_,
                            const float* __restrict__ bias0, float* __restrict__ outm,
                            const float* __restrict__ accu, const float* __restrict__ su_,
                            const float* __restrict__ bias1, float* __restrict__ outu)
{
    int i = blockIdx.x * blockDim.x + threadIdx.x;
    const int NMH = NM * HD;
    const int NTH = (NM + NU) * HD;
    if (i >= NTH) return;

    const float* acc; const float* sbuf; const float* bias; float* out; int j;
    if (i < NMH) { acc = accm; sbuf = sm_; bias = bias0; out = outm; j = i; }
    else         { acc = accu; sbuf = su_; bias = bias1; out = outu; j = i - NMH; }

    float inv = 1.f / (sbuf[j >> 6] + 1e-16f);
    float x = acc[j] * inv + bias[j & 63];
    const float SCALE = 1.0507009873554805f;
    const float SA    = 1.7580993408473766f;   // scale * alpha
    out[j] = x > 0.f ? SCALE * x : SA * (__expf(x) - 1.f);
}

// ---------------- host ------------------------------------------------------
extern "C" void kernel_launch(void* const* d_in, const int* in_sizes, int n_in,
                              void* d_out, int out_size)
{
    const float* x_user  = (const float*)d_in[0];
    const float* x_movie = (const float*)d_in[1];
    const int*   e_u2m   = (const int*)d_in[2];
    const int*   e_m2u   = (const int*)d_in[3];
    const float* Wl      = (const float*)d_in[4];
    const float* bl      = (const float*)d_in[5];
    const float* Wr      = (const float*)d_in[6];
    const float* br      = (const float*)d_in[7];
    const float* att     = (const float*)d_in[8];
    const float* bias    = (const float*)d_in[9];
    float* out = (float*)d_out;

    float *sm, *su, *accm, *accu, *xlu, *xru, *xlm, *xrm, *xu, *xm;
    cudaGetSymbolAddress((void**)&sm,   g_sm);
    cudaGetSymbolAddress((void**)&su,   g_su);
    cudaGetSymbolAddress((void**)&accm, g_accm);
    cudaGetSymbolAddress((void**)&accu, g_accu);
    cudaGetSymbolAddress((void**)&xlu,  g_xlu);
    cudaGetSymbolAddress((void**)&xru,  g_xru);
    cudaGetSymbolAddress((void**)&xlm,  g_xlm);
    cudaGetSymbolAddress((void**)&xrm,  g_xrm);
    cudaGetSymbolAddress((void**)&xu,   g_xu);
    cudaGetSymbolAddress((void**)&xm,   g_xm);

    const int GU = (NU + 63) / 64;               // 1563 user gemm blocks
    const int GM = (NM + 63) / 64;               // 313 movie gemm blocks
    const int CB = ((long)ET * 16 + 255) / 256;  // 63750 conv blocks per direction
    const int IB = ((NM + NU) * (HD / 4) + 255) / 256;
    const int FB = ((NM + NU) * HD + 255) / 256;

    const float* cu = x_user;
    const float* cm = x_movie;

    for (int l = 0; l < 2; l++) {
        int p0 = l * 2 + 0;   // user -> movie
        int p1 = l * 2 + 1;   // movie -> user

        // user rows feed: xl(u2m)=X@Wl[p0], xr(m2u)=X@Wr[p1]
        // movie rows feed: xl(m2u)=X@Wl[p1], xr(u2m)=X@Wr[p0]
        gemm2_dual_k<<<GU + GM, 256>>>(cu, cm,
            Wl + (size_t)p0 * 4096, bl + (size_t)p0 * 64,
            Wr + (size_t)p1 * 4096, br + (size_t)p1 * 64,
            Wl + (size_t)p1 * 4096, bl + (size_t)p1 * 64,
            Wr + (size_t)p0 * 4096, br + (size_t)p0 * 64,
            xlu, xru, xlm, xrm, GU);

        init2_k<<<IB, 256>>>(sm, accm, su, accu);

        conv_dual_k<<<2 * CB, 256>>>(e_u2m, e_m2u, xlu, xrm, xlm, xru,
            att + (size_t)p0 * 64, att + (size_t)p1 * 64,
            sm, su, accm, accu, CB);

        float* om = (l == 1) ? (out + (size_t)NU * HD) : xm;
        float* ou = (l == 1) ? out : xu;
        finalize2_k<<<FB, 256>>>(accm, sm, bias + (size_t)p0 * 64, om,
                                 accu, su, bias + (size_t)p1 * 64, ou);

        cu = xu;
        cm = xm;
    }
}